// round 15
// baseline (speedup 1.0000x reference)
#include <cuda_runtime.h>
#include <math_constants.h>

#define NQ      1024
#define LEN     50
#define NJ      974      // NQ - LEN
#define NK      100
#define KT      4        // shapelets per block (2 packed pairs)
#define KTP     2        // k-pairs
#define NTHR    128
#define RJ      8        // consecutive j per thread -> 1024 positions
#define NCHUNK  13       // 52 padded l-steps / 4
#define NWARP   4
#define ALPHA_F (-100.0f)
#define INV_LEN (1.0f / 50.0f)
#define BIGD    1.0e30f

__device__ __forceinline__ void unpack2(unsigned long long v, float& lo, float& hi) {
    asm("mov.b64 {%0, %1}, %2;" : "=f"(lo), "=f"(hi) : "l"(v));
}
// d = a*b + d, two packed fp32 lanes
__device__ __forceinline__ void ffma2(unsigned long long& d,
                                      unsigned long long a, unsigned long long b) {
    asm("fma.rn.f32x2 %0, %1, %2, %0;" : "+l"(d) : "l"(a), "l"(b));
}
// 16B-slot swizzle: permutes slots within each 128B block -> conflict-free
// for the 64B-lane-stride access pattern of the mainloop.
__device__ __forceinline__ int sw(int i) { return i ^ ((i >> 3) & 7); }

__global__ __launch_bounds__(NTHR, 6)
void softmin_shapelet_kernel(const float* __restrict__ x,
                             const float* __restrict__ s,
                             float* __restrict__ out)
{
    __shared__ __align__(16) float2 dup[1088];        // {x[m],x[m]} duplicated, SWIZZLED slots
    __shared__ __align__(16) float  csA[1088];        // csA[m] = csum[m+1] (cumsum of x^2)
    __shared__ __align__(16) float2 spair[KTP][56];   // {s_2kp[l], s_2kp+1[l]}, zero-padded
    __shared__ float ssq_sh[KT];
    __shared__ float warpsum[NWARP];
    __shared__ float redmin[NWARP][KT];
    __shared__ float redsum[NWARP][KT][2];

    const int t    = threadIdx.x;
    const int n    = blockIdx.y;
    const int k0   = blockIdx.x * KT;
    const int warp = t >> 5;
    const int lane = t & 31;

    // ---- stage x: load 8 values, write duplicated pairs (swizzled slots) ----
    const float4* xg = (const float4*)(x + (size_t)n * NQ);
    float4 a0 = xg[2 * t], a1 = xg[2 * t + 1];
    float v[8] = {a0.x, a0.y, a0.z, a0.w, a1.x, a1.y, a1.z, a1.w};

    float4* dup4 = (float4*)dup;                      // 16B slots, 544 total
    #pragma unroll
    for (int q = 0; q < 4; q++)
        dup4[sw(4 * t + q)] = make_float4(v[2 * q], v[2 * q], v[2 * q + 1], v[2 * q + 1]);
    if (t < 32) dup4[sw(512 + t)] = make_float4(0.f, 0.f, 0.f, 0.f);       // dup[1024..1087]
    if (t < 16) ((float4*)csA)[256 + t] = make_float4(0.f, 0.f, 0.f, 0.f); // csA[1024..1087]

    // ---- stage shapelet k-pairs, zero-padded ----
    for (int i = t; i < KTP * 56; i += NTHR) {
        int kp = i / 56, l = i - kp * 56;
        float va = (l < LEN) ? s[(size_t)(k0 + 2 * kp)     * LEN + l] : 0.0f;
        float vb = (l < LEN) ? s[(size_t)(k0 + 2 * kp + 1) * LEN + l] : 0.0f;
        spair[kp][l] = make_float2(va, vb);
    }

    // ---- per-thread prefix of x^2, then block scan ----
    float p[8];
    p[0] = v[0] * v[0];
    #pragma unroll
    for (int i = 1; i < 8; i++) p[i] = fmaf(v[i], v[i], p[i - 1]);
    float tot = p[7], inc = tot;
    #pragma unroll
    for (int off = 1; off < 32; off <<= 1) {
        float o = __shfl_up_sync(0xFFFFFFFFu, inc, off);
        if (lane >= off) inc += o;
    }
    if (lane == 31) warpsum[warp] = inc;
    __syncthreads();

    float base = 0.0f;
    #pragma unroll
    for (int w = 0; w < NWARP - 1; w++) base += (w < warp) ? warpsum[w] : 0.0f;
    const float ex = base + inc - tot;               // csum at position 8t
    ((float4*)csA)[2 * t]     = make_float4(ex + p[0], ex + p[1], ex + p[2], ex + p[3]);
    ((float4*)csA)[2 * t + 1] = make_float4(ex + p[4], ex + p[5], ex + p[6], ex + p[7]);

    if (t < KT) {                                    // shapelet self-energy
        const int kp = t >> 1, comp = t & 1;
        float aq = 0.0f;
        #pragma unroll
        for (int l = 0; l < LEN; l++) {
            float sv = comp ? spair[kp][l].y : spair[kp][l].x;
            aq = fmaf(sv, sv, aq);
        }
        ssq_sh[t] = aq;
    }
    __syncthreads();

    // ---- sq_win BEFORE mainloop (p/v die here; only sq[8] stays live) ----
    float sq[RJ];
    #pragma unroll
    for (int i = 0; i < RJ; i++) {
        float ce = csA[8 * t + 49 + i];              // csum[8t+i+50]
        float cs = (i == 0) ? ex : ex + p[i - 1];    // csum[8t+i]
        sq[i] = ce - cs;                             // window energy
    }

    // ---- mainloop: aligned 64-bit SMEM pair operands, swizzled x stream ----
    unsigned long long acc2[RJ][KTP];
    #pragma unroll
    for (int jj = 0; jj < RJ; jj++)
        #pragma unroll
        for (int kp = 0; kp < KTP; kp++) acc2[jj][kp] = 0ull;

    const ulonglong2* dup2 = (const ulonglong2*)dup;
    unsigned long long d[12];                        // dup[8t+4c .. 8t+4c+11]
    {
        ulonglong2 q0 = dup2[sw(4 * t + 0)], q1 = dup2[sw(4 * t + 1)], q2 = dup2[sw(4 * t + 2)];
        ulonglong2 q3 = dup2[sw(4 * t + 3)], q4 = dup2[sw(4 * t + 4)], q5 = dup2[sw(4 * t + 5)];
        d[0] = q0.x; d[1]  = q0.y; d[2]  = q1.x; d[3]  = q1.y;
        d[4] = q2.x; d[5]  = q2.y; d[6]  = q3.x; d[7]  = q3.y;
        d[8] = q4.x; d[9]  = q4.y; d[10] = q5.x; d[11] = q5.y;
    }

    #pragma unroll
    for (int c = 0; c < NCHUNK; c++) {
        unsigned long long sd[KTP][4];
        #pragma unroll
        for (int kp = 0; kp < KTP; kp++) {
            const ulonglong2* sp = (const ulonglong2*)spair[kp];
            ulonglong2 pa = sp[2 * c], pb = sp[2 * c + 1];   // warp-broadcast, conflict-free
            sd[kp][0] = pa.x; sd[kp][1] = pa.y; sd[kp][2] = pb.x; sd[kp][3] = pb.y;
        }
        #pragma unroll
        for (int dl = 0; dl < 4; dl++)
            #pragma unroll
            for (int jj = 0; jj < RJ; jj++)
                #pragma unroll
                for (int kp = 0; kp < KTP; kp++)
                    ffma2(acc2[jj][kp], d[jj + dl], sd[kp][dl]);
        if (c < NCHUNK - 1) {
            #pragma unroll
            for (int i = 0; i < 8; i++) d[i] = d[i + 4];
            ulonglong2 qa = dup2[sw(4 * t + 2 * c + 6)], qb = dup2[sw(4 * t + 2 * c + 7)];
            d[8] = qa.x; d[9] = qa.y; d[10] = qb.x; d[11] = qb.y;
        }
    }

    // ---- convert acc -> D exactly once; invalid j masked with BIGD ----
    const float ssqi0 = ssq_sh[0] * INV_LEN, ssqi1 = ssq_sh[1] * INV_LEN;
    const float ssqi2 = ssq_sh[2] * INV_LEN, ssqi3 = ssq_sh[3] * INV_LEN;
    const float M2INV = -2.0f * INV_LEN;

    float D[RJ][KT];
    #pragma unroll
    for (int jj = 0; jj < RJ; jj++) {
        const bool valid = (8 * t + jj < NJ);
        const float bb = sq[jj] * INV_LEN;
        #pragma unroll
        for (int kp = 0; kp < KTP; kp++) {
            float ca, cb;
            unpack2(acc2[jj][kp], ca, cb);
            float Da = fmaf(ca, M2INV, bb + ((kp == 0) ? ssqi0 : ssqi2));
            float Db = fmaf(cb, M2INV, bb + ((kp == 0) ? ssqi1 : ssqi3));
            D[jj][2 * kp]     = valid ? Da : BIGD;
            D[jj][2 * kp + 1] = valid ? Db : BIGD;
        }
    }

    // ---- pass 1: block min per k ----
    float gmin[KT];
    #pragma unroll
    for (int k = 0; k < KT; k++) {
        float mv = D[0][k];
        #pragma unroll
        for (int jj = 1; jj < RJ; jj++) mv = fminf(mv, D[jj][k]);
        #pragma unroll
        for (int off = 16; off > 0; off >>= 1)
            mv = fminf(mv, __shfl_xor_sync(0xFFFFFFFFu, mv, off));
        if (lane == 0) redmin[warp][k] = mv;
    }
    __syncthreads();
    #pragma unroll
    for (int k = 0; k < KT; k++) {
        float mv = redmin[0][k];
        #pragma unroll
        for (int w = 1; w < NWARP; w++) mv = fminf(mv, redmin[w][k]);
        gmin[k] = mv;
    }

    // ---- pass 2: softmin sums (branch-free) ----
    float swt[KT], swd[KT];
    #pragma unroll
    for (int k = 0; k < KT; k++) { swt[k] = 0.0f; swd[k] = 0.0f; }

    #pragma unroll
    for (int jj = 0; jj < RJ; jj++) {
        #pragma unroll
        for (int k = 0; k < KT; k++) {
            float dd = D[jj][k] - gmin[k];
            float w  = __expf(ALPHA_F * dd);       // exactly 0 when dd huge
            swt[k] += w;
            swd[k]  = fmaf(w, dd, swd[k]);
        }
    }

    #pragma unroll
    for (int k = 0; k < KT; k++) {
        #pragma unroll
        for (int off = 16; off > 0; off >>= 1) {
            swt[k] += __shfl_xor_sync(0xFFFFFFFFu, swt[k], off);
            swd[k] += __shfl_xor_sync(0xFFFFFFFFu, swd[k], off);
        }
        if (lane == 0) { redsum[warp][k][0] = swt[k]; redsum[warp][k][1] = swd[k]; }
    }
    __syncthreads();

    if (t < KT) {
        float SW = 0.0f, SWD = 0.0f;
        #pragma unroll
        for (int w = 0; w < NWARP; w++) {
            SW  += redsum[w][t][0];
            SWD += redsum[w][t][1];
        }
        out[(size_t)n * NK + k0 + t] = SWD / SW;
    }
}

extern "C" void kernel_launch(void* const* d_in, const int* in_sizes, int n_in,
                              void* d_out, int out_size)
{
    const float* x = (const float*)d_in[0];   // (512, 1024)
    const float* s = (const float*)d_in[1];   // (100, 50)
    float* out = (float*)d_out;               // (512, 100)

    dim3 grid(NK / KT, 512);                  // (25, 512)
    softmin_shapelet_kernel<<<grid, NTHR>>>(x, s, out);
}

// round 17
// speedup vs baseline: 1.0276x; 1.0276x over previous
#include <cuda_runtime.h>
#include <math_constants.h>

#define NQ      1024
#define LEN     50
#define NJ      974      // NQ - LEN
#define NK      100
#define KT      4        // shapelets per block (2 packed pairs)
#define KTP     2        // k-pairs
#define NTHR    128
#define RJ      8        // consecutive j per thread -> 1024 positions
#define NWARP   4
#define ALPHA_F (-100.0f)
#define INV_LEN (1.0f / 50.0f)
#define BIGD    1.0e30f

__device__ __forceinline__ void unpack2(unsigned long long v, float& lo, float& hi) {
    asm("mov.b64 {%0, %1}, %2;" : "=f"(lo), "=f"(hi) : "l"(v));
}
// d = a*b + d, two packed fp32 lanes
__device__ __forceinline__ void ffma2(unsigned long long& d,
                                      unsigned long long a, unsigned long long b) {
    asm("fma.rn.f32x2 %0, %1, %2, %0;" : "+l"(d) : "l"(a), "l"(b));
}
// 16B-slot swizzle: permutes slots within each 128B block -> conflict-free
// for the 64B-lane-stride access pattern of the mainloop.
__device__ __forceinline__ int sw(int i) { return i ^ ((i >> 3) & 7); }

__global__ __launch_bounds__(NTHR, 6)
void softmin_shapelet_kernel(const float* __restrict__ x,
                             const float* __restrict__ s,
                             float* __restrict__ out)
{
    __shared__ __align__(16) float2 dup[1088];        // {x[m],x[m]} duplicated, SWIZZLED slots
    __shared__ __align__(16) float  csA[1088];        // csA[m] = csum[m+1] (cumsum of x^2)
    __shared__ __align__(16) float2 spair[KTP][56];   // {s_2kp[l], s_2kp+1[l]}, zero-padded
    __shared__ float ssq_sh[KT];
    __shared__ float warpsum[NWARP];
    __shared__ float redmin[NWARP][KT];
    __shared__ float redsum[NWARP][KT][2];

    const int t    = threadIdx.x;
    const int n    = blockIdx.y;
    const int k0   = blockIdx.x * KT;
    const int warp = t >> 5;
    const int lane = t & 31;

    // ---- stage x: load 8 values, write duplicated pairs (swizzled slots) ----
    const float4* xg = (const float4*)(x + (size_t)n * NQ);
    float4 a0 = xg[2 * t], a1 = xg[2 * t + 1];
    float v[8] = {a0.x, a0.y, a0.z, a0.w, a1.x, a1.y, a1.z, a1.w};

    float4* dup4 = (float4*)dup;                      // 16B slots, 544 total
    #pragma unroll
    for (int q = 0; q < 4; q++)
        dup4[sw(4 * t + q)] = make_float4(v[2 * q], v[2 * q], v[2 * q + 1], v[2 * q + 1]);
    if (t < 32) dup4[sw(512 + t)] = make_float4(0.f, 0.f, 0.f, 0.f);       // dup[1024..1087]
    if (t < 16) ((float4*)csA)[256 + t] = make_float4(0.f, 0.f, 0.f, 0.f); // csA[1024..1087]

    // ---- stage shapelet k-pairs, zero-padded ----
    for (int i = t; i < KTP * 56; i += NTHR) {
        int kp = i / 56, l = i - kp * 56;
        float va = (l < LEN) ? s[(size_t)(k0 + 2 * kp)     * LEN + l] : 0.0f;
        float vb = (l < LEN) ? s[(size_t)(k0 + 2 * kp + 1) * LEN + l] : 0.0f;
        spair[kp][l] = make_float2(va, vb);
    }

    // ---- per-thread prefix of x^2, then block scan ----
    float p[8];
    p[0] = v[0] * v[0];
    #pragma unroll
    for (int i = 1; i < 8; i++) p[i] = fmaf(v[i], v[i], p[i - 1]);
    float tot = p[7], inc = tot;
    #pragma unroll
    for (int off = 1; off < 32; off <<= 1) {
        float o = __shfl_up_sync(0xFFFFFFFFu, inc, off);
        if (lane >= off) inc += o;
    }
    if (lane == 31) warpsum[warp] = inc;
    __syncthreads();

    float base = 0.0f;
    #pragma unroll
    for (int w = 0; w < NWARP - 1; w++) base += (w < warp) ? warpsum[w] : 0.0f;
    const float ex = base + inc - tot;               // csum at position 8t
    ((float4*)csA)[2 * t]     = make_float4(ex + p[0], ex + p[1], ex + p[2], ex + p[3]);
    ((float4*)csA)[2 * t + 1] = make_float4(ex + p[4], ex + p[5], ex + p[6], ex + p[7]);

    if (t < KT) {                                    // shapelet self-energy
        const int kp = t >> 1, comp = t & 1;
        float aq = 0.0f;
        #pragma unroll
        for (int l = 0; l < LEN; l++) {
            float sv = comp ? spair[kp][l].y : spair[kp][l].x;
            aq = fmaf(sv, sv, aq);
        }
        ssq_sh[t] = aq;
    }
    __syncthreads();

    // ---- sq_win BEFORE mainloop (p/v die here; only sq[8] stays live) ----
    float sq[RJ];
    #pragma unroll
    for (int i = 0; i < RJ; i++) {
        float ce = csA[8 * t + 49 + i];              // csum[8t+i+50]
        float cs = (i == 0) ? ex : ex + p[i - 1];    // csum[8t+i]
        sq[i] = ce - cs;                             // window energy
    }

    // ---- mainloop: ring-buffered x stream (no shift MOVs), swizzled slots ----
    // Local value m = x[8t+m] pair; lives in d[m % 12]. Chunk c (l = 4c+dl)
    // uses values m = 4c + jj + dl. All indices compile-time after unroll.
    unsigned long long acc2[RJ][KTP];
    #pragma unroll
    for (int jj = 0; jj < RJ; jj++)
        #pragma unroll
        for (int kp = 0; kp < KTP; kp++) acc2[jj][kp] = 0ull;

    const ulonglong2* dup2 = (const ulonglong2*)dup;
    unsigned long long d[12];                        // ring: value m at d[m % 12]
    #pragma unroll
    for (int sl = 0; sl < 6; sl++) {                 // values 0..11
        ulonglong2 q = dup2[sw(4 * t + sl)];
        d[2 * sl] = q.x; d[2 * sl + 1] = q.y;
    }

    #pragma unroll
    for (int c = 0; c < 12; c++) {                   // full chunks: l = 4c .. 4c+3
        unsigned long long sd[KTP][4];
        #pragma unroll
        for (int kp = 0; kp < KTP; kp++) {
            const ulonglong2* sp = (const ulonglong2*)spair[kp];
            ulonglong2 pa = sp[2 * c], pb = sp[2 * c + 1];   // warp-broadcast
            sd[kp][0] = pa.x; sd[kp][1] = pa.y; sd[kp][2] = pb.x; sd[kp][3] = pb.y;
        }
        #pragma unroll
        for (int dl = 0; dl < 4; dl++)
            #pragma unroll
            for (int jj = 0; jj < RJ; jj++)
                #pragma unroll
                for (int kp = 0; kp < KTP; kp++)
                    ffma2(acc2[jj][kp], d[(4 * c + jj + dl) % 12], sd[kp][dl]);
        // prefetch values 4c+12 .. 4c+15 into the slots just freed
        {
            ulonglong2 qa = dup2[sw(4 * t + 2 * c + 6)];
            ulonglong2 qb = dup2[sw(4 * t + 2 * c + 7)];
            d[(4 * c + 0) % 12] = qa.x; d[(4 * c + 1) % 12] = qa.y;
            d[(4 * c + 2) % 12] = qb.x; d[(4 * c + 3) % 12] = qb.y;
        }
    }
    // tail chunk c=12: only l=48,49 are real (50,51 were zero-pad -> dropped)
    {
        const ulonglong2* sp0 = (const ulonglong2*)spair[0];
        const ulonglong2* sp1 = (const ulonglong2*)spair[1];
        ulonglong2 pa0 = sp0[24], pa1 = sp1[24];     // l = 48, 49
        unsigned long long sd0[2] = {pa0.x, pa0.y};
        unsigned long long sd1[2] = {pa1.x, pa1.y};
        #pragma unroll
        for (int dl = 0; dl < 2; dl++)
            #pragma unroll
            for (int jj = 0; jj < RJ; jj++) {
                ffma2(acc2[jj][0], d[(48 + jj + dl) % 12], sd0[dl]);
                ffma2(acc2[jj][1], d[(48 + jj + dl) % 12], sd1[dl]);
            }
    }

    // ---- convert acc -> D exactly once; invalid j masked with BIGD ----
    const float ssqi0 = ssq_sh[0] * INV_LEN, ssqi1 = ssq_sh[1] * INV_LEN;
    const float ssqi2 = ssq_sh[2] * INV_LEN, ssqi3 = ssq_sh[3] * INV_LEN;
    const float M2INV = -2.0f * INV_LEN;

    float D[RJ][KT];
    #pragma unroll
    for (int jj = 0; jj < RJ; jj++) {
        const bool valid = (8 * t + jj < NJ);
        const float bb = sq[jj] * INV_LEN;
        #pragma unroll
        for (int kp = 0; kp < KTP; kp++) {
            float ca, cb;
            unpack2(acc2[jj][kp], ca, cb);
            float Da = fmaf(ca, M2INV, bb + ((kp == 0) ? ssqi0 : ssqi2));
            float Db = fmaf(cb, M2INV, bb + ((kp == 0) ? ssqi1 : ssqi3));
            D[jj][2 * kp]     = valid ? Da : BIGD;
            D[jj][2 * kp + 1] = valid ? Db : BIGD;
        }
    }

    // ---- pass 1: block min per k ----
    float gmin[KT];
    #pragma unroll
    for (int k = 0; k < KT; k++) {
        float mv = D[0][k];
        #pragma unroll
        for (int jj = 1; jj < RJ; jj++) mv = fminf(mv, D[jj][k]);
        #pragma unroll
        for (int off = 16; off > 0; off >>= 1)
            mv = fminf(mv, __shfl_xor_sync(0xFFFFFFFFu, mv, off));
        if (lane == 0) redmin[warp][k] = mv;
    }
    __syncthreads();
    #pragma unroll
    for (int k = 0; k < KT; k++) {
        float mv = redmin[0][k];
        #pragma unroll
        for (int w = 1; w < NWARP; w++) mv = fminf(mv, redmin[w][k]);
        gmin[k] = mv;
    }

    // ---- pass 2: softmin sums (branch-free) ----
    float swt[KT], swd[KT];
    #pragma unroll
    for (int k = 0; k < KT; k++) { swt[k] = 0.0f; swd[k] = 0.0f; }

    #pragma unroll
    for (int jj = 0; jj < RJ; jj++) {
        #pragma unroll
        for (int k = 0; k < KT; k++) {
            float dd = D[jj][k] - gmin[k];
            float w  = __expf(ALPHA_F * dd);       // exactly 0 when dd huge
            swt[k] += w;
            swd[k]  = fmaf(w, dd, swd[k]);
        }
    }

    #pragma unroll
    for (int k = 0; k < KT; k++) {
        #pragma unroll
        for (int off = 16; off > 0; off >>= 1) {
            swt[k] += __shfl_xor_sync(0xFFFFFFFFu, swt[k], off);
            swd[k] += __shfl_xor_sync(0xFFFFFFFFu, swd[k], off);
        }
        if (lane == 0) { redsum[warp][k][0] = swt[k]; redsum[warp][k][1] = swd[k]; }
    }
    __syncthreads();

    if (t < KT) {
        float SW = 0.0f, SWD = 0.0f;
        #pragma unroll
        for (int w = 0; w < NWARP; w++) {
            SW  += redsum[w][t][0];
            SWD += redsum[w][t][1];
        }
        out[(size_t)n * NK + k0 + t] = SWD / SW;
    }
}

extern "C" void kernel_launch(void* const* d_in, const int* in_sizes, int n_in,
                              void* d_out, int out_size)
{
    const float* x = (const float*)d_in[0];   // (512, 1024)
    const float* s = (const float*)d_in[1];   // (100, 50)
    float* out = (float*)d_out;               // (512, 100)

    dim3 grid(NK / KT, 512);                  // (25, 512)
    softmin_shapelet_kernel<<<grid, NTHR>>>(x, s, out);
}